// round 1
// baseline (speedup 1.0000x reference)
#include <cuda_runtime.h>
#include <cstdint>

// IPLayer segment-sum: out[atom][g] += inter[pair][g] for atom = ind_2[pair][0]
// Inputs (metadata order): ind_2 (int32, N_PAIRS*2), prop (float32, N_ATOMS*128),
//                          inter (float32, N_PAIRS*64). Output: float32 N_ATOMS*64.

#define N_INTER 64

__global__ void zero_out_kernel(float4* __restrict__ out, int n4) {
    int i = blockIdx.x * blockDim.x + threadIdx.x;
    if (i < n4) out[i] = make_float4(0.f, 0.f, 0.f, 0.f);
}

// 4 threads per pair; each thread handles a contiguous 64B quarter (4 x float4)
// of the 256B feature row, and issues 4 independent red.global.add.v4.f32.
__global__ void seg_red_kernel(const int* __restrict__ ind2,
                               const float4* __restrict__ inter,
                               float* __restrict__ out,
                               int n_work /* = n_pairs*4 */) {
    int i = blockIdx.x * blockDim.x + threadIdx.x;
    if (i >= n_work) return;
    int p = i >> 2;          // pair index
    int q = i & 3;           // quarter within the 64-float row

    int atom = __ldg(&ind2[2 * p]);

    const float4* src = inter + (size_t)p * (N_INTER / 4) + q * 4;
    float* dst = out + (size_t)atom * N_INTER + q * 16;

    float4 v0 = src[0];
    float4 v1 = src[1];
    float4 v2 = src[2];
    float4 v3 = src[3];

    asm volatile("red.global.add.v4.f32 [%0], {%1,%2,%3,%4};"
                 :: "l"(dst + 0), "f"(v0.x), "f"(v0.y), "f"(v0.z), "f"(v0.w) : "memory");
    asm volatile("red.global.add.v4.f32 [%0], {%1,%2,%3,%4};"
                 :: "l"(dst + 4), "f"(v1.x), "f"(v1.y), "f"(v1.z), "f"(v1.w) : "memory");
    asm volatile("red.global.add.v4.f32 [%0], {%1,%2,%3,%4};"
                 :: "l"(dst + 8), "f"(v2.x), "f"(v2.y), "f"(v2.z), "f"(v2.w) : "memory");
    asm volatile("red.global.add.v4.f32 [%0], {%1,%2,%3,%4};"
                 :: "l"(dst + 12), "f"(v3.x), "f"(v3.y), "f"(v3.z), "f"(v3.w) : "memory");
}

extern "C" void kernel_launch(void* const* d_in, const int* in_sizes, int n_in,
                              void* d_out, int out_size) {
    const int*    ind2  = (const int*)d_in[0];
    const float4* inter = (const float4*)d_in[2];
    float*        out   = (float*)d_out;

    int n_pairs = in_sizes[0] / 2;

    // Zero the (poisoned) output buffer.
    int n4 = out_size / 4;
    zero_out_kernel<<<(n4 + 255) / 256, 256>>>((float4*)out, n4);

    // Scatter-add with vector reductions.
    int n_work = n_pairs * 4;
    seg_red_kernel<<<(n_work + 255) / 256, 256>>>(ind2, inter, out, n_work);
}

// round 6
// speedup vs baseline: 1.9752x; 1.9752x over previous
#include <cuda_runtime.h>
#include <cstdint>

// IPLayer segment-sum: out[atom][g] += inter[pair][g] for atom = ind_2[pair][0]
// Inputs (metadata order): ind_2 (int32, N_PAIRS*2), prop (float32, N_ATOMS*128),
//                          inter (float32, N_PAIRS*64). Output: float32 N_ATOMS*64.

#define N_INTER 64

__global__ void zero_out_kernel(float4* __restrict__ out, int n4) {
    int i = blockIdx.x * blockDim.x + threadIdx.x;
    if (i < n4) out[i] = make_float4(0.f, 0.f, 0.f, 0.f);
}

// 16 threads per pair; each thread owns ONE 16B float4 chunk of the 256B row
// and issues exactly one red.global.add.v4.f32. Adjacent lanes in the same
// instruction write adjacent 16B -> dense 32B sectors, fully coalesced 256B
// atomic groups per pair, and perfectly coalesced float4 loads from inter.
__global__ void seg_red_kernel(const int* __restrict__ ind2,
                               const float4* __restrict__ inter,
                               float* __restrict__ out,
                               int n_work /* = n_pairs*16 */) {
    int i = blockIdx.x * blockDim.x + threadIdx.x;
    if (i >= n_work) return;
    int p = i >> 4;          // pair index
    int c = i & 15;          // float4 chunk within the 64-float row

    int atom = __ldg(&ind2[2 * p]);

    float4 v = inter[(size_t)p * (N_INTER / 4) + c];
    float* dst = out + (size_t)atom * N_INTER + c * 4;

    asm volatile("red.global.add.v4.f32 [%0], {%1,%2,%3,%4};"
                 :: "l"(dst), "f"(v.x), "f"(v.y), "f"(v.z), "f"(v.w) : "memory");
}

extern "C" void kernel_launch(void* const* d_in, const int* in_sizes, int n_in,
                              void* d_out, int out_size) {
    const int*    ind2  = (const int*)d_in[0];
    const float4* inter = (const float4*)d_in[2];
    float*        out   = (float*)d_out;

    int n_pairs = in_sizes[0] / 2;

    // Zero the (poisoned) output buffer.
    int n4 = out_size / 4;
    zero_out_kernel<<<(n4 + 255) / 256, 256>>>((float4*)out, n4);

    // Scatter-add with one dense, coalesced red.v4 per thread.
    int n_work = n_pairs * 16;
    seg_red_kernel<<<(n_work + 255) / 256, 256>>>(ind2, inter, out, n_work);
}

// round 7
// speedup vs baseline: 2.1412x; 1.0840x over previous
#include <cuda_runtime.h>
#include <cstdint>

// IPLayer segment-sum: out[atom][g] += inter[pair][g] for atom = ind_2[pair][0]
// Inputs (metadata order): ind_2 (int32, N_PAIRS*2), prop (float32, N_ATOMS*128),
//                          inter (float32, N_PAIRS*64). Output: float32 N_ATOMS*64.

#define N_INTER 64
#define PP      4   // pairs per thread

__global__ void zero_out_kernel(float4* __restrict__ out, int n4) {
    int i = blockIdx.x * blockDim.x + threadIdx.x;
    if (i < n4) out[i] = make_float4(0.f, 0.f, 0.f, 0.f);
}

// 16 lanes cover one pair's 256B row (one float4 chunk per lane, dense sectors).
// Each thread handles PP consecutive pairs for the SAME chunk c: 4 independent
// index loads + 4 independent float4 loads are issued up front (MLP=4+),
// then 4 red.global.add.v4.f32. Traffic is unchanged vs the 1-pair version;
// this is purely latency hiding.
__global__ void seg_red_kernel(const int* __restrict__ ind2,
                               const float4* __restrict__ inter,
                               float* __restrict__ out,
                               int n_pairs) {
    int i = blockIdx.x * blockDim.x + threadIdx.x;
    int g = i >> 4;          // pair-group index (PP pairs)
    int c = i & 15;          // float4 chunk within the 64-float row
    int p0 = g * PP;
    if (p0 >= n_pairs) return;

    if (p0 + PP <= n_pairs) {
        // Fast path: full group of PP pairs.
        int a0 = __ldg(&ind2[2 * (p0 + 0)]);
        int a1 = __ldg(&ind2[2 * (p0 + 1)]);
        int a2 = __ldg(&ind2[2 * (p0 + 2)]);
        int a3 = __ldg(&ind2[2 * (p0 + 3)]);

        const float4* src = inter + (size_t)p0 * (N_INTER / 4) + c;
        float4 v0 = src[0 * (N_INTER / 4)];
        float4 v1 = src[1 * (N_INTER / 4)];
        float4 v2 = src[2 * (N_INTER / 4)];
        float4 v3 = src[3 * (N_INTER / 4)];

        float* d0 = out + (size_t)a0 * N_INTER + c * 4;
        float* d1 = out + (size_t)a1 * N_INTER + c * 4;
        float* d2 = out + (size_t)a2 * N_INTER + c * 4;
        float* d3 = out + (size_t)a3 * N_INTER + c * 4;

        asm volatile("red.global.add.v4.f32 [%0], {%1,%2,%3,%4};"
                     :: "l"(d0), "f"(v0.x), "f"(v0.y), "f"(v0.z), "f"(v0.w) : "memory");
        asm volatile("red.global.add.v4.f32 [%0], {%1,%2,%3,%4};"
                     :: "l"(d1), "f"(v1.x), "f"(v1.y), "f"(v1.z), "f"(v1.w) : "memory");
        asm volatile("red.global.add.v4.f32 [%0], {%1,%2,%3,%4};"
                     :: "l"(d2), "f"(v2.x), "f"(v2.y), "f"(v2.z), "f"(v2.w) : "memory");
        asm volatile("red.global.add.v4.f32 [%0], {%1,%2,%3,%4};"
                     :: "l"(d3), "f"(v3.x), "f"(v3.y), "f"(v3.z), "f"(v3.w) : "memory");
    } else {
        // Tail: per-pair.
        for (int p = p0; p < n_pairs; p++) {
            int a = __ldg(&ind2[2 * p]);
            float4 v = inter[(size_t)p * (N_INTER / 4) + c];
            float* dst = out + (size_t)a * N_INTER + c * 4;
            asm volatile("red.global.add.v4.f32 [%0], {%1,%2,%3,%4};"
                         :: "l"(dst), "f"(v.x), "f"(v.y), "f"(v.z), "f"(v.w) : "memory");
        }
    }
}

extern "C" void kernel_launch(void* const* d_in, const int* in_sizes, int n_in,
                              void* d_out, int out_size) {
    const int*    ind2  = (const int*)d_in[0];
    const float4* inter = (const float4*)d_in[2];
    float*        out   = (float*)d_out;

    int n_pairs = in_sizes[0] / 2;

    // Zero the (poisoned) output buffer.
    int n4 = out_size / 4;
    zero_out_kernel<<<(n4 + 255) / 256, 256>>>((float4*)out, n4);

    // Scatter-add: 16 lanes x PP pairs per thread.
    int n_groups = (n_pairs + PP - 1) / PP;
    long long n_work = (long long)n_groups * 16;
    int blocks = (int)((n_work + 255) / 256);
    seg_red_kernel<<<blocks, 256>>>(ind2, inter, out, n_pairs);
}